// round 8
// baseline (speedup 1.0000x reference)
#include <cuda_runtime.h>
#include <cuda_bf16.h>
#include <stdint.h>

#define BB 8192

// ---------------------------------------------------------------------------
// Device scratch (no cudaMalloc allowed)
// ---------------------------------------------------------------------------
// Activation images: bf16 hi/lo, pre-swizzled SMEM-tile layout
// [rowblk(128 rows)][chunk(64 k)][16384 bytes]
__device__ __nv_bfloat16 g_x_h [BB * 512], g_x_l [BB * 512];
__device__ __nv_bfloat16 g_h1_h[BB * 128], g_h1_l[BB * 128];
__device__ __nv_bfloat16 g_h2_h[BB * 512], g_h2_l[BB * 512];
__device__ __nv_bfloat16 g_h3_h[BB * 128], g_h3_l[BB * 128];
__device__ __nv_bfloat16 g_h4_h[BB * 64],  g_h4_l[BB * 64];
__device__ float g_know[BB * 64];

// Knowledge-branch compaction scratch
__device__ int  g_bstart[BB + 1];
__device__ int2 g_rowlist[BB * 50];
__device__ float g_part[2 * BB * 64];

// Pre-split + pre-swizzled weight images ([N][K] K-major, SW128 64x64 tiles)
__device__ __nv_bfloat16 g_Wkg_h[4096],  g_Wkg_l[4096];
__device__ __nv_bfloat16 g_W1a_h[65536], g_W1a_l[65536];
__device__ __nv_bfloat16 g_W1b_h[65536], g_W1b_l[65536];
__device__ __nv_bfloat16 g_W1c_h[65536], g_W1c_l[65536];
__device__ __nv_bfloat16 g_W1d_h[8192],  g_W1d_l[8192];
__device__ __nv_bfloat16 g_W2_h[65536],  g_W2_l[65536];

// ---------------------------------------------------------------------------
// Helpers
// ---------------------------------------------------------------------------
__device__ __forceinline__ uint32_t smem_u32(const void* p) {
    uint32_t a;
    asm("{ .reg .u64 t; cvta.to.shared.u64 t, %1; cvt.u32.u64 %0, t; }"
        : "=r"(a) : "l"(p));
    return a;
}

#define SWZ(x) ((x) ^ (((x) >> 3) & 0x70))

#define CP16(dst, src) \
    asm volatile("cp.async.cg.shared.global [%0], [%1], 16;" \
                 :: "r"(dst), "l"(src) : "memory")
#define CP_COMMIT() asm volatile("cp.async.commit_group;" ::: "memory")
#define CP_WAIT1()  asm volatile("cp.async.wait_group 1;" ::: "memory")
#define CP_WAIT0()  asm volatile("cp.async.wait_group 0;" ::: "memory")

__device__ __forceinline__ uint32_t packbf(float e0, float e1) {
    uint32_t r;
    asm("cvt.rn.bf16x2.f32 %0, %1, %2;" : "=r"(r) : "f"(e1), "f"(e0));
    return r; // low half = e0, high half = e1
}
__device__ __forceinline__ float lof(uint32_t p) { return __uint_as_float(p << 16); }
__device__ __forceinline__ float hif(uint32_t p) { return __uint_as_float(p & 0xffff0000u); }

__device__ __forceinline__ void split8(float4 a, float4 b, uint4& H, uint4& L) {
    uint32_t h0 = packbf(a.x, a.y), h1 = packbf(a.z, a.w);
    uint32_t h2 = packbf(b.x, b.y), h3 = packbf(b.z, b.w);
    L.x = packbf(a.x - lof(h0), a.y - hif(h0));
    L.y = packbf(a.z - lof(h1), a.w - hif(h1));
    L.z = packbf(b.x - lof(h2), b.y - hif(h2));
    L.w = packbf(b.z - lof(h3), b.w - hif(h3));
    H.x = h0; H.y = h1; H.z = h2; H.w = h3;
}

__device__ __forceinline__ void ldsm4(uint32_t* r, uint32_t addr) {
    asm volatile("ldmatrix.sync.aligned.m8n8.x4.shared.b16 {%0,%1,%2,%3}, [%4];"
        : "=r"(r[0]), "=r"(r[1]), "=r"(r[2]), "=r"(r[3]) : "r"(addr));
}

__device__ __forceinline__ void mma16816(float* d, const uint32_t* a,
                                         const uint32_t* b) {
    asm volatile(
        "mma.sync.aligned.m16n8k16.row.col.f32.bf16.bf16.f32 "
        "{%0,%1,%2,%3}, {%4,%5,%6,%7}, {%8,%9}, {%0,%1,%2,%3};"
        : "+f"(d[0]), "+f"(d[1]), "+f"(d[2]), "+f"(d[3])
        : "r"(a[0]), "r"(a[1]), "r"(a[2]), "r"(a[3]), "r"(b[0]), "r"(b[1]));
}

// Shared 128x64x64 3-term MMA over one SMEM stage.
// Stage layout: Ah@0 (16K), Al@16K, Bh@32K (8K), Bl@40K (8K).
// Warp grid 4(m) x 2(n); warp tile 32x32.
__device__ __forceinline__ void mma_block(uint32_t sbase, int lane, int wm,
                                          int wn, float (&acc)[2][4][4]) {
    const int a_r  = lane & 15;
    const int a_cb = (lane >> 4) << 4;
    const int b_r  = ((lane >> 4) << 3) + (lane & 7);
    const int b_cb = ((lane >> 3) & 1) << 4;
#pragma unroll
    for (int ks = 0; ks < 4; ks++) {
        uint32_t bh0[4], bh1[4], bl0[4], bl1[4];
        uint32_t ba0 = sbase + 32768 + SWZ((uint32_t)(wn * 32 + b_r) * 128 + ks * 32 + b_cb);
        uint32_t ba1 = sbase + 32768 + SWZ((uint32_t)(wn * 32 + 16 + b_r) * 128 + ks * 32 + b_cb);
        ldsm4(bh0, ba0); ldsm4(bh1, ba1);
        ldsm4(bl0, ba0 + 8192); ldsm4(bl1, ba1 + 8192);
#pragma unroll
        for (int mi = 0; mi < 2; mi++) {
            uint32_t ah[4], al[4];
            uint32_t aa = sbase + SWZ((uint32_t)(wm * 32 + mi * 16 + a_r) * 128 + ks * 32 + a_cb);
            ldsm4(ah, aa);
            ldsm4(al, aa + 16384);
#pragma unroll
            for (int ni = 0; ni < 4; ni++) {
                const uint32_t* bh = (ni < 2) ? (bh0 + 2 * ni) : (bh1 + 2 * (ni - 2));
                const uint32_t* bl = (ni < 2) ? (bl0 + 2 * ni) : (bl1 + 2 * (ni - 2));
                mma16816(acc[mi][ni], ah, bh);
                mma16816(acc[mi][ni], al, bh);
                mma16816(acc[mi][ni], ah, bl);
            }
        }
    }
}

// ---------------------------------------------------------------------------
// Weight prep
// ---------------------------------------------------------------------------
struct PrepArgs {
    const float* src[6];
    __nv_bfloat16 *hi[6], *lo[6];
    int kdim[6], n[6];
    int off[7];
};

__global__ __launch_bounds__(256) void prep_weights(PrepArgs a) {
    int e = blockIdx.x * 256 + threadIdx.x;
#pragma unroll
    for (int sgi = 0; sgi < 6; sgi++) {
        if (e >= a.off[sgi] && e < a.off[sgi + 1]) {
            int le = e - a.off[sgi];
            int N = a.n[sgi], KD = a.kdim[sgi];
            int k = le / N, n = le % N;
            float v = a.src[sgi][le];
            __nv_bfloat16 h = __float2bfloat16_rn(v);
            __nv_bfloat16 l = __float2bfloat16_rn(v - __bfloat162float(h));
            int nt = n >> 6, nl = n & 63, c = k >> 6, kl = k & 63;
            int tile = nt * (KD >> 6) + c;
            uint32_t boff = (uint32_t)nl * 128 + (uint32_t)kl * 2;
            uint32_t so = SWZ(boff);
            int di = tile * 4096 + (int)(so >> 1);
            a.hi[sgi][di] = h;
            a.lo[sgi][di] = l;
        }
    }
}

// x -> split bf16 image layout
__global__ __launch_bounds__(256) void prep_x(const float* __restrict__ x,
                                              __nv_bfloat16* __restrict__ xh,
                                              __nv_bfloat16* __restrict__ xl) {
    int e = blockIdx.x * 256 + threadIdx.x;       // 8192*512
    int r = e >> 9, k = e & 511;
    float v = x[e];
    __nv_bfloat16 h = __float2bfloat16_rn(v);
    __nv_bfloat16 l = __float2bfloat16_rn(v - __bfloat162float(h));
    int c = k >> 6, kl = k & 63;
    size_t boff = ((size_t)(r >> 7) * 8 + c) * 16384
                + SWZ((uint32_t)(r & 127) * 128 + kl * 2);
    xh[boff >> 1] = h;
    xl[boff >> 1] = l;
}

// ---------------------------------------------------------------------------
// Knowledge compaction
// ---------------------------------------------------------------------------
__global__ __launch_bounds__(256) void scan_counts(const int* __restrict__ mask,
                                                   int* __restrict__ bstart) {
    __shared__ int sums[256];
    int t = threadIdx.x;
    int local[32];
    int base = t * 32;
    int acc = 0;
#pragma unroll 1
    for (int i = 0; i < 32; i++) {
        const int* m = mask + (size_t)(base + i) * 50;
        int cnt = 0;
#pragma unroll
        for (int k = 0; k < 50; k++) cnt += (m[k] != 0);
        local[i] = acc;
        acc += cnt;
    }
    sums[t] = acc;
    __syncthreads();
    if (t == 0) {
        int run = 0;
        for (int i = 0; i < 256; i++) { int v = sums[i]; sums[i] = run; run += v; }
        bstart[BB] = run;
    }
    __syncthreads();
    int off = sums[t];
#pragma unroll 1
    for (int i = 0; i < 32; i++) bstart[base + i] = off + local[i];
}

__global__ __launch_bounds__(256) void fill_rows(const int* __restrict__ mask,
                                                 const int* __restrict__ idx,
                                                 const int* __restrict__ bstart,
                                                 int2* __restrict__ rowlist) {
    int b = blockIdx.x * 256 + threadIdx.x;       // 8192
    int pos = bstart[b];
#pragma unroll 1
    for (int k = 0; k < 50; k++) {
        if (mask[(size_t)b * 50 + k]) {
            rowlist[pos] = make_int2(b, idx[(size_t)b * 50 + k]);
            pos++;
        }
    }
}

// Tile kernel: 128 compacted rows -> gather+split -> MMA vs Wkg ->
// relu(+bkg) -> segmented per-batch column sums -> partials.
// SMEM: Gh@0 16K, Gl@16K, Wh@32K 8K, Wl@40K 8K, bS@49152 (512B),
//       red@49664 (128x65 f32 = 33280B). Total 82944.
__global__ __launch_bounds__(256, 2) void tkn_tiles(
    const float* __restrict__ kg, const int2* __restrict__ rowlist,
    const int* __restrict__ bstart,
    const __nv_bfloat16* __restrict__ Wh, const __nv_bfloat16* __restrict__ Wl,
    const float* __restrict__ bkg, float* __restrict__ part)
{
    extern __shared__ char smem[];
    const int total = bstart[BB];
    const int row0 = blockIdx.x * 128;
    if (row0 >= total) return;

    const uint32_t sb = smem_u32(smem);
    const int t = threadIdx.x, lane = t & 31, wid = t >> 5;
    const int wm = wid & 3, wn = wid >> 2;
    int* bS = (int*)(smem + 49152);
    float* red = (float*)(smem + 49664);

    // Gather + split (2 threads per row)
    {
        const int row = t >> 1, half = t & 1;
        int ridx = row0 + row;
        int b = -1, kgix = -1;
        if (ridx < total) { int2 e = rowlist[ridx]; b = e.x; kgix = e.y; }
        if (half == 0) bS[row] = b;
        if (kgix >= 0) {
            const float4* src = (const float4*)(kg + (size_t)kgix * 64 + half * 32);
#pragma unroll
            for (int g = 0; g < 4; g++) {
                uint4 H, L;
                split8(src[2 * g], src[2 * g + 1], H, L);
                uint32_t so = SWZ((uint32_t)row * 128 + half * 64 + g * 16);
                *(uint4*)(smem + so)         = H;
                *(uint4*)(smem + 16384 + so) = L;
            }
        } else {
            uint4 Z = make_uint4(0, 0, 0, 0);
#pragma unroll
            for (int g = 0; g < 4; g++) {
                uint32_t so = SWZ((uint32_t)row * 128 + half * 64 + g * 16);
                *(uint4*)(smem + so)         = Z;
                *(uint4*)(smem + 16384 + so) = Z;
            }
        }
        // Wkg images
#pragma unroll
        for (int i = 0; i < 2; i++) {
            int e = t + i * 256;
            *(uint4*)(smem + 32768 + e * 16) = ((const uint4*)Wh)[e];
            *(uint4*)(smem + 40960 + e * 16) = ((const uint4*)Wl)[e];
        }
    }
    __syncthreads();

    float acc[2][4][4];
#pragma unroll
    for (int i = 0; i < 2; i++)
#pragma unroll
        for (int j = 0; j < 4; j++)
#pragma unroll
            for (int e = 0; e < 4; e++) acc[i][j][e] = 0.f;

    mma_block(sb, lane, wm, wn, acc);

    // relu(z + bkg) -> red
    const int g4 = lane >> 2, q = lane & 3;
#pragma unroll
    for (int mi = 0; mi < 2; mi++) {
        int rl0 = wm * 32 + mi * 16 + g4;
#pragma unroll
        for (int ni = 0; ni < 4; ni++) {
            int cl = wn * 32 + ni * 8 + q * 2;
            float b0 = __ldg(bkg + cl), b1 = __ldg(bkg + cl + 1);
            red[rl0 * 65 + cl]           = fmaxf(acc[mi][ni][0] + b0, 0.f);
            red[rl0 * 65 + cl + 1]       = fmaxf(acc[mi][ni][1] + b1, 0.f);
            red[(rl0 + 8) * 65 + cl]     = fmaxf(acc[mi][ni][2] + b0, 0.f);
            red[(rl0 + 8) * 65 + cl + 1] = fmaxf(acc[mi][ni][3] + b1, 0.f);
        }
    }
    __syncthreads();

    // Segmented per-batch reduce (threads 0..63, one per column)
    if (t < 64) {
        int c = t;
        float s = 0.f;
        int bcur = bS[0];
#pragma unroll 1
        for (int r = 0; r < 128; r++) {
            int b = bS[r];
            if (b != bcur) {
                if (bcur >= 0) {
                    int slot = ((bstart[bcur] >> 7) == (int)blockIdx.x) ? 0 : 1;
                    part[(size_t)slot * (BB * 64) + (size_t)bcur * 64 + c] = s;
                }
                s = 0.f;
                bcur = b;
            }
            if (b < 0) break;
            s += red[r * 65 + c];
        }
        if (bcur >= 0) {
            int slot = ((bstart[bcur] >> 7) == (int)blockIdx.x) ? 0 : 1;
            part[(size_t)slot * (BB * 64) + (size_t)bcur * 64 + c] = s;
        }
    }
}

__global__ __launch_bounds__(256) void combine_know(const int* __restrict__ bstart,
                                                    const float* __restrict__ part,
                                                    float* __restrict__ know) {
    int e = blockIdx.x * 256 + threadIdx.x;       // 8192*64
    int b = e >> 6, c = e & 63;
    int s = bstart[b], en = bstart[b + 1];
    float v = 0.f;
    if (en > s) {
        v = part[(size_t)b * 64 + c];
        if ((s >> 7) != ((en - 1) >> 7))
            v += part[(size_t)(BB * 64) + (size_t)b * 64 + c];
    }
    know[e] = v;
}

// ---------------------------------------------------------------------------
// cp.async stage fill: A tile 16K hi + 16K lo, B tile 8K hi + 8K lo
// ---------------------------------------------------------------------------
__device__ __forceinline__ void stage_issue(uint32_t sb, int s, int t,
                                            const char* ah, const char* al,
                                            const char* bh, const char* bl) {
    uint32_t d = sb + (uint32_t)s * 49152u;
#pragma unroll
    for (int i = 0; i < 4; i++) {
        uint32_t o = (uint32_t)(t + i * 256) * 16;
        CP16(d + o, ah + o);
        CP16(d + 16384 + o, al + o);
    }
#pragma unroll
    for (int i = 0; i < 2; i++) {
        uint32_t o = (uint32_t)(t + i * 256) * 16;
        CP16(d + 32768 + o, bh + o);
        CP16(d + 40960 + o, bl + o);
    }
    CP_COMMIT();
}

// ---------------------------------------------------------------------------
// GEMM: images in -> act -> images out (or fp32 for final layer)
// 256 threads, 128x64 CTA tile, warp tile 32x32, double-buffered cp.async.
// ---------------------------------------------------------------------------
template <int CHUNKS, int OUT_CH, bool RELU, bool ADD, bool F32OUT>
__global__ __launch_bounds__(256, 2) void tgemm2(
    const __nv_bfloat16* __restrict__ Ah_img,
    const __nv_bfloat16* __restrict__ Al_img,
    const __nv_bfloat16* __restrict__ Bh_img,
    const __nv_bfloat16* __restrict__ Bl_img,
    const float* __restrict__ bias,
    const float* __restrict__ addsrc,
    __nv_bfloat16* __restrict__ Oh,
    __nv_bfloat16* __restrict__ Ol,
    float* __restrict__ C)
{
    constexpr int NTOT = OUT_CH * 64;
    extern __shared__ char smem[];
    const uint32_t sb = smem_u32(smem);
    const int t = threadIdx.x, lane = t & 31, wid = t >> 5;
    const int wm = wid & 3, wn = wid >> 2;
    const int rowblk = blockIdx.y, nt = blockIdx.x;
    const int row0 = rowblk * 128, col0 = nt * 64;

    float acc[2][4][4];
#pragma unroll
    for (int i = 0; i < 2; i++)
#pragma unroll
        for (int j = 0; j < 4; j++)
#pragma unroll
            for (int e = 0; e < 4; e++) acc[i][j][e] = 0.f;

    const char* Ah0 = (const char*)Ah_img + (size_t)rowblk * CHUNKS * 16384;
    const char* Al0 = (const char*)Al_img + (size_t)rowblk * CHUNKS * 16384;
    const char* Bh0 = (const char*)Bh_img + (size_t)nt * CHUNKS * 8192;
    const char* Bl0 = (const char*)Bl_img + (size_t)nt * CHUNKS * 8192;

    stage_issue(sb, 0, t, Ah0, Al0, Bh0, Bl0);

#pragma unroll 1
    for (int c = 0; c < CHUNKS; c++) {
        const int s = c & 1;
        if (c + 1 < CHUNKS) {
            stage_issue(sb, 1 - s, t,
                        Ah0 + (size_t)(c + 1) * 16384, Al0 + (size_t)(c + 1) * 16384,
                        Bh0 + (size_t)(c + 1) * 8192,  Bl0 + (size_t)(c + 1) * 8192);
            CP_WAIT1();
        } else {
            CP_WAIT0();
        }
        __syncthreads();
        mma_block(sb + (uint32_t)s * 49152u, lane, wm, wn, acc);
        __syncthreads();
    }

    // Epilogue
    const int g4 = lane >> 2, q = lane & 3;
    const size_t ob = ((size_t)rowblk * OUT_CH + nt) * 16384;
#pragma unroll
    for (int mi = 0; mi < 2; mi++) {
        int rl0 = wm * 32 + mi * 16 + g4;
#pragma unroll
        for (int ni = 0; ni < 4; ni++) {
            int cl = wn * 32 + ni * 8 + q * 2;
            float b0 = __ldg(bias + col0 + cl), b1 = __ldg(bias + col0 + cl + 1);
            float v00 = acc[mi][ni][0] + b0, v01 = acc[mi][ni][1] + b1;
            float v10 = acc[mi][ni][2] + b0, v11 = acc[mi][ni][3] + b1;
            if (RELU) {
                v00 = fmaxf(v00, 0.f); v01 = fmaxf(v01, 0.f);
                v10 = fmaxf(v10, 0.f); v11 = fmaxf(v11, 0.f);
            }
            if (ADD) {
                float2 a0 = *(const float2*)&addsrc[(size_t)(row0 + rl0) * 64 + cl];
                float2 a1 = *(const float2*)&addsrc[(size_t)(row0 + rl0 + 8) * 64 + cl];
                v00 += a0.x; v01 += a0.y; v10 += a1.x; v11 += a1.y;
            }
            if (F32OUT) {
                *(float2*)&C[(size_t)(row0 + rl0) * NTOT + col0 + cl] = make_float2(v00, v01);
                *(float2*)&C[(size_t)(row0 + rl0 + 8) * NTOT + col0 + cl] = make_float2(v10, v11);
            } else {
                uint32_t h0 = packbf(v00, v01);
                uint32_t l0 = packbf(v00 - lof(h0), v01 - hif(h0));
                uint32_t o0 = SWZ((uint32_t)rl0 * 128 + cl * 2);
                *(uint32_t*)((char*)Oh + ob + o0) = h0;
                *(uint32_t*)((char*)Ol + ob + o0) = l0;
                uint32_t h1 = packbf(v10, v11);
                uint32_t l1 = packbf(v10 - lof(h1), v11 - hif(h1));
                uint32_t o1 = SWZ((uint32_t)(rl0 + 8) * 128 + cl * 2);
                *(uint32_t*)((char*)Oh + ob + o1) = h1;
                *(uint32_t*)((char*)Ol + ob + o1) = l1;
            }
        }
    }
}

// ---------------------------------------------------------------------------
// Launch
// ---------------------------------------------------------------------------
extern "C" void kernel_launch(void* const* d_in, const int* in_sizes, int n_in,
                              void* d_out, int out_size)
{
    const float* x   = (const float*)d_in[0];
    const float* kg  = (const float*)d_in[1];
    const int*   idx = (const int*)  d_in[2];
    const int*   msk = (const int*)  d_in[3];
    const float* Wkg = (const float*)d_in[4];
    const float* bkg = (const float*)d_in[5];
    const float* W1a = (const float*)d_in[6];
    const float* b1a = (const float*)d_in[7];
    const float* W1b = (const float*)d_in[8];
    const float* b1b = (const float*)d_in[9];
    const float* W1c = (const float*)d_in[10];
    const float* b1c = (const float*)d_in[11];
    const float* W1d = (const float*)d_in[12];
    const float* b1d = (const float*)d_in[13];
    const float* W2  = (const float*)d_in[14];
    const float* b2  = (const float*)d_in[15];
    float* out = (float*)d_out;

    __nv_bfloat16 *xh, *xl, *h1h, *h1l, *h2h, *h2l, *h3h, *h3l, *h4h, *h4l;
    float *know, *part;
    int *bstart; int2 *rowlist;
    cudaGetSymbolAddress((void**)&xh,  g_x_h);  cudaGetSymbolAddress((void**)&xl,  g_x_l);
    cudaGetSymbolAddress((void**)&h1h, g_h1_h); cudaGetSymbolAddress((void**)&h1l, g_h1_l);
    cudaGetSymbolAddress((void**)&h2h, g_h2_h); cudaGetSymbolAddress((void**)&h2l, g_h2_l);
    cudaGetSymbolAddress((void**)&h3h, g_h3_h); cudaGetSymbolAddress((void**)&h3l, g_h3_l);
    cudaGetSymbolAddress((void**)&h4h, g_h4_h); cudaGetSymbolAddress((void**)&h4l, g_h4_l);
    cudaGetSymbolAddress((void**)&know, g_know);
    cudaGetSymbolAddress((void**)&part, g_part);
    cudaGetSymbolAddress((void**)&bstart, g_bstart);
    cudaGetSymbolAddress((void**)&rowlist, g_rowlist);

    __nv_bfloat16 *wkgh, *wkgl, *w1ah, *w1al, *w1bh, *w1bl, *w1ch, *w1cl,
                  *w1dh, *w1dl, *w2h, *w2l;
    cudaGetSymbolAddress((void**)&wkgh, g_Wkg_h); cudaGetSymbolAddress((void**)&wkgl, g_Wkg_l);
    cudaGetSymbolAddress((void**)&w1ah, g_W1a_h); cudaGetSymbolAddress((void**)&w1al, g_W1a_l);
    cudaGetSymbolAddress((void**)&w1bh, g_W1b_h); cudaGetSymbolAddress((void**)&w1bl, g_W1b_l);
    cudaGetSymbolAddress((void**)&w1ch, g_W1c_h); cudaGetSymbolAddress((void**)&w1cl, g_W1c_l);
    cudaGetSymbolAddress((void**)&w1dh, g_W1d_h); cudaGetSymbolAddress((void**)&w1dl, g_W1d_l);
    cudaGetSymbolAddress((void**)&w2h,  g_W2_h);  cudaGetSymbolAddress((void**)&w2l,  g_W2_l);

    const int GEMM_SMEM = 98304;   // 2 stages x 48K
    const int KNOW_SMEM = 82944;
    cudaFuncSetAttribute(tgemm2<8, 2, true,  false, false>, cudaFuncAttributeMaxDynamicSharedMemorySize, GEMM_SMEM);
    cudaFuncSetAttribute(tgemm2<2, 8, true,  false, false>, cudaFuncAttributeMaxDynamicSharedMemorySize, GEMM_SMEM);
    cudaFuncSetAttribute(tgemm2<2, 1, true,  true,  false>, cudaFuncAttributeMaxDynamicSharedMemorySize, GEMM_SMEM);
    cudaFuncSetAttribute(tgemm2<1, 16, false, false, true>, cudaFuncAttributeMaxDynamicSharedMemorySize, GEMM_SMEM);
    cudaFuncSetAttribute(tkn_tiles, cudaFuncAttributeMaxDynamicSharedMemorySize, KNOW_SMEM);

    // Weight prep
    PrepArgs pa;
    pa.src[0] = Wkg; pa.hi[0] = wkgh; pa.lo[0] = wkgl; pa.kdim[0] = 64;  pa.n[0] = 64;
    pa.src[1] = W1a; pa.hi[1] = w1ah; pa.lo[1] = w1al; pa.kdim[1] = 512; pa.n[1] = 128;
    pa.src[2] = W1b; pa.hi[2] = w1bh; pa.lo[2] = w1bl; pa.kdim[2] = 128; pa.n[2] = 512;
    pa.src[3] = W1c; pa.hi[3] = w1ch; pa.lo[3] = w1cl; pa.kdim[3] = 512; pa.n[3] = 128;
    pa.src[4] = W1d; pa.hi[4] = w1dh; pa.lo[4] = w1dl; pa.kdim[4] = 128; pa.n[4] = 64;
    pa.src[5] = W2;  pa.hi[5] = w2h;  pa.lo[5] = w2l;  pa.kdim[5] = 64;  pa.n[5] = 1024;
    pa.off[0] = 0;      pa.off[1] = 4096;   pa.off[2] = 69632;  pa.off[3] = 135168;
    pa.off[4] = 200704; pa.off[5] = 208896; pa.off[6] = 274432;
    prep_weights<<<1072, 256>>>(pa);
    prep_x<<<BB * 512 / 256, 256>>>(x, xh, xl);

    // Knowledge branch (compacted)
    scan_counts<<<1, 256>>>(msk, bstart);
    fill_rows<<<32, 256>>>(msk, idx, bstart, rowlist);
    tkn_tiles<<<(BB * 50 + 127) / 128, 256, KNOW_SMEM>>>(kg, rowlist, bstart,
                                                         wkgh, wkgl, bkg, part);
    combine_know<<<BB * 64 / 256, 256>>>(bstart, part, know);

    // MLP chain
    tgemm2<8, 2, true,  false, false><<<dim3(2, 64),  256, GEMM_SMEM>>>(xh,  xl,  w1ah, w1al, b1a, nullptr, h1h, h1l, nullptr);
    tgemm2<2, 8, true,  false, false><<<dim3(8, 64),  256, GEMM_SMEM>>>(h1h, h1l, w1bh, w1bl, b1b, nullptr, h2h, h2l, nullptr);
    tgemm2<8, 2, true,  false, false><<<dim3(2, 64),  256, GEMM_SMEM>>>(h2h, h2l, w1ch, w1cl, b1c, nullptr, h3h, h3l, nullptr);
    tgemm2<2, 1, true,  true,  false><<<dim3(1, 64),  256, GEMM_SMEM>>>(h3h, h3l, w1dh, w1dl, b1d, know,    h4h, h4l, nullptr);
    tgemm2<1, 16, false, false, true ><<<dim3(16, 64), 256, GEMM_SMEM>>>(h4h, h4l, w2h,  w2l,  b2,  nullptr, nullptr, nullptr, out);
}